// round 2
// baseline (speedup 1.0000x reference)
#include <cuda_runtime.h>
#include <math.h>

// theta [B=4] degrees, image [C=3, H=80, W=80] -> out [B, C, H, W].
// Dense tent-weight matmul in the reference == bilinear gather with
// zero weight for taps outside the grid (tent support <= 2 integer taps).

#define B_ 4
#define C_ 3
#define H_ 80
#define W_ 80

__global__ __launch_bounds__(256) void rot_bilinear_kernel(
    const float* __restrict__ theta,   // [B]
    const float* __restrict__ image,   // [C, H, W]
    float* __restrict__ out)           // [B, C, H, W]
{
    // grid is sized exactly: 100 blocks * 256 threads == 4*80*80, no guard.
    const int t = blockIdx.x * blockDim.x + threadIdx.x;

    const int x = t % W_;
    const int y = (t / W_) % H_;
    const int b = t / (H_ * W_);        // uniform within a CTA (6400 % 256 == 0)

    const float cx = (W_ - 1) * 0.5f;
    const float cy = (H_ - 1) * 0.5f;

    const float th = __ldg(theta + b) * 0.017453292519943295f;  // deg2rad
    float s, c;
    __sincosf(th, &s, &c);               // MUFU fast path, ~5e-7 abs err

    const float x_rel = (float)x - cx;
    const float y_rel = (float)y - cy;

    const float sx = fmaf(c, x_rel, fmaf(s, y_rel, cx));   //  cos*x + sin*y + cx
    const float sy = fmaf(-s, x_rel, fmaf(c, y_rel, cy));  // -sin*x + cos*y + cy

    const int ix0 = __float2int_rd(sx);
    const int iy0 = __float2int_rd(sy);
    const int ix1 = ix0 + 1;
    const int iy1 = iy0 + 1;
    const float ax = sx - __int2float_rn(ix0);   // weight of ix1
    const float ay = sy - __int2float_rn(iy0);   // weight of iy1

    float wx0 = 1.0f - ax, wx1 = ax;
    float wy0 = 1.0f - ay, wy1 = ay;
    // zero weights for out-of-grid taps (matches reference's truncated tent sum)
    if (ix0 < 0 || ix0 >= W_) wx0 = 0.0f;
    if (ix1 < 0 || ix1 >= W_) wx1 = 0.0f;
    if (iy0 < 0 || iy0 >= H_) wy0 = 0.0f;
    if (iy1 < 0 || iy1 >= H_) wy1 = 0.0f;

    // clamp indices so loads stay in-bounds (weight already zeroed)
    const int jx0 = min(max(ix0, 0), W_ - 1);
    const int jx1 = min(max(ix1, 0), W_ - 1);
    const int jy0 = min(max(iy0, 0), H_ - 1);
    const int jy1 = min(max(iy1, 0), H_ - 1);

    const float w00 = wy0 * wx0;
    const float w01 = wy0 * wx1;
    const float w10 = wy1 * wx0;
    const float w11 = wy1 * wx1;

    const int o00 = jy0 * W_ + jx0;
    const int o01 = jy0 * W_ + jx1;
    const int o10 = jy1 * W_ + jx0;
    const int o11 = jy1 * W_ + jx1;

    float* outp = out + ((b * C_) * H_ + y) * W_ + x;

    #pragma unroll
    for (int ch = 0; ch < C_; ch++) {
        const float* img = image + ch * (H_ * W_);
        float v = w00 * __ldg(img + o00);
        v = fmaf(w01, __ldg(img + o01), v);
        v = fmaf(w10, __ldg(img + o10), v);
        v = fmaf(w11, __ldg(img + o11), v);
        outp[ch * (H_ * W_)] = v;
    }
}

extern "C" void kernel_launch(void* const* d_in, const int* in_sizes, int n_in,
                              void* d_out, int out_size) {
    const float* theta = (const float*)d_in[0];   // [4]
    const float* image = (const float*)d_in[1];   // [3, 80, 80]
    float* out = (float*)d_out;                   // [4, 3, 80, 80]

    rot_bilinear_kernel<<<100, 256>>>(theta, image, out);  // exactly 25600 threads
}